// round 5
// baseline (speedup 1.0000x reference)
#include <cuda_runtime.h>
#include <cuda_bf16.h>
#include <math.h>
#include <stdint.h>

// Problem constants (fixed by the reference)
#define NN 50000
#define HH 256
#define TT 4
#define LL 2
#define SS 3
#define CC 3
#define H3 (3 * HH)
#define THX (TT * HH)   // 1024

// ---------------- fp32 scratch: ONE device global, carved by offsets --------
#define OFF_H    ((size_t)0)                        // [NN*HH]    node state
#define OFF_A4   (OFF_H    + (size_t)NN * HH)       // [NN*THX]   per-etype aggregates (gh aliases)
#define OFF_A    (OFF_A4   + (size_t)NN * THX)      // [NN*HH]    combined messages
#define OFF_GX   (OFF_A    + (size_t)NN * HH)       // [NN*H3]    a @ w_ih.T
#define OFF_CNT  (OFF_GX   + (size_t)NN * H3)       // [NN*TT]    per-(node,etype) edge counts
#define OFF_POOL (OFF_CNT  + (size_t)NN * TT)       // [HH]
#define SCRATCH_FLOATS (OFF_POOL + HH)
__device__ float s_scratch[SCRATCH_FLOATS];

// bf16 split weights
__device__ __nv_bfloat16 s_Whi[(size_t)LL * HH * THX];   // Wbig: [l][k][t*H+j]
__device__ __nv_bfloat16 s_Wlo[(size_t)LL * HH * THX];
__device__ __nv_bfloat16 s_wihi[(size_t)LL * H3 * HH];
__device__ __nv_bfloat16 s_wilo[(size_t)LL * H3 * HH];
__device__ __nv_bfloat16 s_whhi[(size_t)LL * H3 * HH];
__device__ __nv_bfloat16 s_whlo[(size_t)LL * H3 * HH];

// ---------------- generic helpers ----------------
__global__ void copy_kernel(const float* __restrict__ in, float* __restrict__ out, size_t n4) {
    size_t i = (size_t)blockIdx.x * blockDim.x + threadIdx.x;
    if (i < n4) ((float4*)out)[i] = ((const float4*)in)[i];
}

__global__ void zero_kernel(float* __restrict__ p, size_t n4) {
    size_t i = (size_t)blockIdx.x * blockDim.x + threadIdx.x;
    if (i < n4) ((float4*)p)[i] = make_float4(0.f, 0.f, 0.f, 0.f);
}

// fp32 -> bf16 hi + bf16 residual lo (same layout)
__global__ void split_kernel(const float* __restrict__ w, __nv_bfloat16* __restrict__ hi,
                             __nv_bfloat16* __restrict__ lo, int n) {
    int i = blockIdx.x * blockDim.x + threadIdx.x;
    if (i >= n) return;
    float v = w[i];
    __nv_bfloat16 h = __float2bfloat16_rn(v);
    hi[i] = h;
    lo[i] = __float2bfloat16_rn(v - __bfloat162float(h));
}

// repack W_lin [L,T,H,H] (l,t,k,j) -> Wbig [l][k][t*H+j], with bf16 split
__global__ void repack_split_kernel(const float* __restrict__ W,
                                    __nv_bfloat16* __restrict__ hi,
                                    __nv_bfloat16* __restrict__ lo, int n) {
    int i = blockIdx.x * blockDim.x + threadIdx.x;
    if (i >= n) return;
    int l = i / (HH * THX);
    int rem = i - l * (HH * THX);
    int k = rem / THX;
    int ti = rem - k * THX;
    int t = ti >> 8;          // /HH
    int j = ti & 255;         // %HH
    float v = W[(((size_t)l * TT + t) * HH + k) * HH + j];
    __nv_bfloat16 h = __float2bfloat16_rn(v);
    hi[i] = h;
    lo[i] = __float2bfloat16_rn(v - __bfloat162float(h));
}

// ---------------- bf16x3 tensor-core GEMM ----------------
// C[M,Nc] = A[M,K] @ B^T (B is [Nc,K] bf16 hi/lo) + bias[Nc] (bias may be null)
#define GBM 128
#define GBN 128
#define GBK 32
#define SROW 20   // smem row stride in uint32 (16 data + 4 pad)

__device__ __forceinline__ void mma16816(float* c, const uint32_t* a, const uint32_t* b) {
    asm volatile(
        "mma.sync.aligned.m16n8k16.row.col.f32.bf16.bf16.f32 "
        "{%0,%1,%2,%3}, {%4,%5,%6,%7}, {%8,%9}, {%0,%1,%2,%3};"
        : "+f"(c[0]), "+f"(c[1]), "+f"(c[2]), "+f"(c[3])
        : "r"(a[0]), "r"(a[1]), "r"(a[2]), "r"(a[3]), "r"(b[0]), "r"(b[1]));
}

__device__ __forceinline__ uint32_t pack_hi2(float x, float y) {
    __nv_bfloat162 p;
    p.x = __float2bfloat16_rn(x);
    p.y = __float2bfloat16_rn(y);
    return *reinterpret_cast<uint32_t*>(&p);
}
__device__ __forceinline__ uint32_t pack_lo2(float x, float y, uint32_t hp) {
    __nv_bfloat162 h = *reinterpret_cast<__nv_bfloat162*>(&hp);
    __nv_bfloat162 p;
    p.x = __float2bfloat16_rn(x - __bfloat162float(h.x));
    p.y = __float2bfloat16_rn(y - __bfloat162float(h.y));
    return *reinterpret_cast<uint32_t*>(&p);
}

__global__ __launch_bounds__(256)
void mma_gemm_kernel(const float* __restrict__ A,
                     const __nv_bfloat16* __restrict__ Bhi,
                     const __nv_bfloat16* __restrict__ Blo,
                     const float* __restrict__ bias, float* __restrict__ C,
                     int M, int Nc, int K) {
    __shared__ uint32_t Ash[GBM][SROW];
    __shared__ uint32_t Asl[GBM][SROW];
    __shared__ uint32_t Bsh[GBN][SROW];
    __shared__ uint32_t Bsl[GBN][SROW];

    const int tid = threadIdx.x;
    const int lane = tid & 31;
    const int wid = tid >> 5;
    const int wm = (wid >> 2) * 64;
    const int wn = (wid & 3) * 32;
    const int g = lane >> 2;
    const int t = lane & 3;

    const int blockRow = blockIdx.y * GBM;
    const int blockCol = blockIdx.x * GBN;

    const uint32_t* B32h = (const uint32_t*)Bhi;
    const uint32_t* B32l = (const uint32_t*)Blo;
    const int Kw = K >> 1;

    float acc[4][4][4];
#pragma unroll
    for (int mi = 0; mi < 4; mi++)
#pragma unroll
        for (int ni = 0; ni < 4; ni++)
#pragma unroll
            for (int r = 0; r < 4; r++) acc[mi][ni][r] = 0.f;

    float4 areg[4];
    uint4 bhr[2], blr[2];

    auto load_stage = [&](int k0) {
#pragma unroll
        for (int i = 0; i < 4; i++) {
            int lin = tid + 256 * i;
            int row = lin >> 3;
            int c4 = lin & 7;
            int gm = blockRow + row;
            areg[i] = (gm < M) ? *(const float4*)&A[(size_t)gm * K + k0 + c4 * 4]
                               : make_float4(0.f, 0.f, 0.f, 0.f);
        }
#pragma unroll
        for (int i = 0; i < 2; i++) {
            int lin = tid + 256 * i;
            int row = lin >> 2;
            int ch = lin & 3;
            size_t gi = (size_t)(blockCol + row) * Kw + (k0 >> 1) + ch * 4;
            bhr[i] = *(const uint4*)&B32h[gi];
            blr[i] = *(const uint4*)&B32l[gi];
        }
    };

    auto store_stage = [&]() {
#pragma unroll
        for (int i = 0; i < 4; i++) {
            int lin = tid + 256 * i;
            int row = lin >> 3;
            int c4 = lin & 7;
            float4 v = areg[i];
            uint32_t h0 = pack_hi2(v.x, v.y);
            uint32_t h1 = pack_hi2(v.z, v.w);
            Ash[row][c4 * 2 + 0] = h0;
            Ash[row][c4 * 2 + 1] = h1;
            Asl[row][c4 * 2 + 0] = pack_lo2(v.x, v.y, h0);
            Asl[row][c4 * 2 + 1] = pack_lo2(v.z, v.w, h1);
        }
#pragma unroll
        for (int i = 0; i < 2; i++) {
            int lin = tid + 256 * i;
            int row = lin >> 2;
            int ch = lin & 3;
            *(uint4*)&Bsh[row][ch * 4] = bhr[i];
            *(uint4*)&Bsl[row][ch * 4] = blr[i];
        }
    };

    load_stage(0);
    const int nStages = K / GBK;
    for (int s = 0; s < nStages; s++) {
        store_stage();
        __syncthreads();
        if (s + 1 < nStages) load_stage((s + 1) * GBK);

#pragma unroll
        for (int ks = 0; ks < 2; ks++) {
            const int base = ks * 8;
            uint32_t ah[4][4], al[4][4], bh_[4][2], bl_[4][2];
#pragma unroll
            for (int mi = 0; mi < 4; mi++) {
                int r0 = wm + mi * 16 + g;
                ah[mi][0] = Ash[r0][base + t];
                ah[mi][1] = Ash[r0 + 8][base + t];
                ah[mi][2] = Ash[r0][base + t + 4];
                ah[mi][3] = Ash[r0 + 8][base + t + 4];
                al[mi][0] = Asl[r0][base + t];
                al[mi][1] = Asl[r0 + 8][base + t];
                al[mi][2] = Asl[r0][base + t + 4];
                al[mi][3] = Asl[r0 + 8][base + t + 4];
            }
#pragma unroll
            for (int ni = 0; ni < 4; ni++) {
                int n0 = wn + ni * 8 + g;
                bh_[ni][0] = Bsh[n0][base + t];
                bh_[ni][1] = Bsh[n0][base + t + 4];
                bl_[ni][0] = Bsl[n0][base + t];
                bl_[ni][1] = Bsl[n0][base + t + 4];
            }
#pragma unroll
            for (int mi = 0; mi < 4; mi++)
#pragma unroll
                for (int ni = 0; ni < 4; ni++) {
                    mma16816(acc[mi][ni], ah[mi], bh_[ni]);
                    mma16816(acc[mi][ni], ah[mi], bl_[ni]);
                    mma16816(acc[mi][ni], al[mi], bh_[ni]);
                }
        }
        __syncthreads();
    }

#pragma unroll
    for (int mi = 0; mi < 4; mi++) {
        int r0 = blockRow + wm + mi * 16 + g;
        int r1 = r0 + 8;
#pragma unroll
        for (int ni = 0; ni < 4; ni++) {
            int col = blockCol + wn + ni * 8 + t * 2;
            float b0 = bias ? bias[col] : 0.f;
            float b1 = bias ? bias[col + 1] : 0.f;
            if (r0 < M) {
                float2 v = make_float2(acc[mi][ni][0] + b0, acc[mi][ni][1] + b1);
                *(float2*)&C[(size_t)r0 * Nc + col] = v;
            }
            if (r1 < M) {
                float2 v = make_float2(acc[mi][ni][2] + b0, acc[mi][ni][3] + b1);
                *(float2*)&C[(size_t)r1 * Nc + col] = v;
            }
        }
    }
}

// ---------------- edge scatter (pre-transform): A4[dst, et*H..] += h[src] ----
__global__ void scatter2_kernel(const float* __restrict__ h,
                                const int* __restrict__ src,
                                const int* __restrict__ dst,
                                const int* __restrict__ et,
                                float* __restrict__ A4,
                                float* __restrict__ counts, int E) {
    int gwarp = (int)(((size_t)blockIdx.x * blockDim.x + threadIdx.x) >> 5);
    int lane = threadIdx.x & 31;
    if (gwarp >= E) return;
    int s = __ldg(&src[gwarp]);
    int d = __ldg(&dst[gwarp]);
    int t = __ldg(&et[gwarp]);
    const float4* sp = (const float4*)(h + (size_t)s * HH);
    float4* dp = (float4*)(A4 + (size_t)d * THX + (size_t)t * HH);
#pragma unroll
    for (int i = 0; i < 2; i++) {
        float4 v = sp[lane + 32 * i];
        asm volatile("red.global.add.v4.f32 [%0], {%1,%2,%3,%4};"
                     :: "l"(dp + lane + 32 * i), "f"(v.x), "f"(v.y), "f"(v.z), "f"(v.w)
                     : "memory");
    }
    if (lane == 0)
        asm volatile("red.global.add.f32 [%0], %1;"
                     :: "l"(counts + (size_t)d * TT + t), "f"(1.0f) : "memory");
}

// a[n,k] += sum_t counts[n,t] * blin[t*H + k]  (bias generality; zero in practice)
__global__ void bias_corr_kernel(float* __restrict__ a, const float* __restrict__ counts,
                                 const float* __restrict__ blin, int total) {
    int idx = blockIdx.x * blockDim.x + threadIdx.x;
    if (idx >= total) return;
    int n = idx >> 8;
    int k = idx & 255;
    const float* c = counts + (size_t)n * TT;
    float corr = c[0] * blin[k] + c[1] * blin[HH + k] + c[2] * blin[2 * HH + k]
               + c[3] * blin[3 * HH + k];
    a[idx] += corr;
}

// ---------------- GRU gates (elementwise, float4-vectorized) ----------------
__global__ void gru_kernel(const float4* __restrict__ gx, const float4* __restrict__ gh,
                           float4* __restrict__ h, int total4) {
    int idx = blockIdx.x * blockDim.x + threadIdx.x;
    if (idx >= total4) return;
    int n = idx >> 6;
    int k = idx & 63;
    const float4* gxr = gx + (size_t)n * 192;
    const float4* ghr = gh + (size_t)n * 192;
    float4 xr = gxr[k], xz = gxr[64 + k], xn = gxr[128 + k];
    float4 hr = ghr[k], hz = ghr[64 + k], hn = ghr[128 + k];
    float4 hv = h[idx];
    float4 out;
#define GRU1(c)                                                       \
    {                                                                 \
        float r = 1.f / (1.f + expf(-(xr.c + hr.c)));                 \
        float z = 1.f / (1.f + expf(-(xz.c + hz.c)));                 \
        float nng = tanhf(xn.c + r * hn.c);                           \
        out.c = (1.f - z) * nng + z * hv.c;                           \
    }
    GRU1(x) GRU1(y) GRU1(z) GRU1(w)
#undef GRU1
    h[idx] = out;
}

// ---------------- pooling + FC ----------------
__global__ void pool_kernel(const float* __restrict__ h, float* __restrict__ pooled, int n) {
    int k = threadIdx.x;
    float acc = 0.f;
    for (int r = blockIdx.x; r < n; r += gridDim.x)
        acc += h[(size_t)r * HH + k];
    atomicAdd(&pooled[k], acc);
}

__global__ void fc_kernel(const float* __restrict__ pooled, const float* __restrict__ fc_w,
                          const float* __restrict__ fc_b, float* __restrict__ out, float invN) {
    int c = blockIdx.x;
    int lane = threadIdx.x;
    float acc = 0.f;
    for (int k = lane; k < HH; k += 32) acc += pooled[k] * fc_w[c * HH + k];
#pragma unroll
    for (int o = 16; o; o >>= 1) acc += __shfl_xor_sync(0xffffffffu, acc, o);
    if (lane == 0) out[c] = acc * invN + fc_b[c];
}

// ---------------- host orchestration ----------------
extern "C" void kernel_launch(void* const* d_in, const int* in_sizes, int n_in,
                              void* d_out, int out_size) {
    const float* x      = (const float*)d_in[0];
    const int*   src    = (const int*)d_in[1];
    const int*   dst    = (const int*)d_in[2];
    const int*   etype  = (const int*)d_in[3];
    const float* W_lin  = (const float*)d_in[4];   // [L,T,H,H]
    const float* b_lin  = (const float*)d_in[5];   // [L,T,H]
    const float* w_ih   = (const float*)d_in[6];   // [L,3H,H]
    const float* w_hh   = (const float*)d_in[7];   // [L,3H,H]
    const float* b_ih   = (const float*)d_in[8];   // [L,3H]
    const float* b_hh   = (const float*)d_in[9];   // [L,3H]
    const float* fc_w   = (const float*)d_in[10];  // [C,H]
    const float* fc_b   = (const float*)d_in[11];  // [C]
    float* out = (float*)d_out;

    const int E = in_sizes[1];

    float* base = nullptr;
    cudaGetSymbolAddress((void**)&base, s_scratch);
    float* p_h      = base + OFF_H;
    float* p_A4     = base + OFF_A4;
    float* p_gh     = base + OFF_A4;   // alias: A4 dead after GEMM1, gh made after
    float* p_a      = base + OFF_A;
    float* p_gx     = base + OFF_GX;
    float* p_cnt    = base + OFF_CNT;
    float* p_pooled = base + OFF_POOL;

    __nv_bfloat16 *p_Whi, *p_Wlo, *p_wihi, *p_wilo, *p_whhi, *p_whlo;
    cudaGetSymbolAddress((void**)&p_Whi, s_Whi);
    cudaGetSymbolAddress((void**)&p_Wlo, s_Wlo);
    cudaGetSymbolAddress((void**)&p_wihi, s_wihi);
    cudaGetSymbolAddress((void**)&p_wilo, s_wilo);
    cudaGetSymbolAddress((void**)&p_whhi, s_whhi);
    cudaGetSymbolAddress((void**)&p_whlo, s_whlo);

    // ---- weight repack/splits (once per launch) ----
    {
        int nW = LL * HH * THX;
        int nG = LL * H3 * HH;
        repack_split_kernel<<<(nW + 255) / 256, 256>>>(W_lin, p_Whi, p_Wlo, nW);
        split_kernel<<<(nG + 255) / 256, 256>>>(w_ih, p_wihi, p_wilo, nG);
        split_kernel<<<(nG + 255) / 256, 256>>>(w_hh, p_whhi, p_whlo, nG);
    }

    // ---- h = x ----
    size_t n4 = (size_t)NN * HH / 4;
    copy_kernel<<<(int)((n4 + 255) / 256), 256>>>(x, p_h, n4);

    dim3 grid_a(HH / GBN, (NN + GBM - 1) / GBM);     // (2, 391)  a = A4 @ Wbig^T
    dim3 grid_g(H3 / GBN, (NN + GBM - 1) / GBM);     // (6, 391)
    int scatter_blocks = (int)(((size_t)E * 32 + 255) / 256);
    int gru_blocks = (int)((n4 + 255) / 256);
    size_t a4_4 = (size_t)NN * THX / 4;
    size_t cnt4 = (size_t)NN * TT / 4;

    for (int l = 0; l < LL; l++) {
        const float* blinL = b_lin + (size_t)l * THX;
        const float* bihL  = b_ih + (size_t)l * H3;
        const float* bhhL  = b_hh + (size_t)l * H3;
        const __nv_bfloat16* Whl  = p_Whi + (size_t)l * HH * THX;
        const __nv_bfloat16* Wll  = p_Wlo + (size_t)l * HH * THX;
        const __nv_bfloat16* wihl = p_wihi + (size_t)l * H3 * HH;
        const __nv_bfloat16* will = p_wilo + (size_t)l * H3 * HH;
        const __nv_bfloat16* whhl = p_whhi + (size_t)l * H3 * HH;
        const __nv_bfloat16* whll = p_whlo + (size_t)l * H3 * HH;

        for (int s = 0; s < SS; s++) {
            // A4 = 0 ; counts = 0 ; A4[dst, et] += h[src]
            zero_kernel<<<(int)((a4_4 + 255) / 256), 256>>>(p_A4, a4_4);
            zero_kernel<<<(int)((cnt4 + 255) / 256), 256>>>(p_cnt, cnt4);
            scatter2_kernel<<<scatter_blocks, 256>>>(p_h, src, dst, etype, p_A4, p_cnt, E);
            // a = A4 @ Wbig^T   [N,256], K=1024
            mma_gemm_kernel<<<grid_a, 256>>>(p_A4, Whl, Wll, nullptr, p_a, NN, HH, THX);
            bias_corr_kernel<<<(NN * HH + 255) / 256, 256>>>(p_a, p_cnt, blinL, NN * HH);
            // gx = a @ w_ih^T + b_ih ; gh = h @ w_hh^T + b_hh (gh overwrites A4)
            mma_gemm_kernel<<<grid_g, 256>>>(p_a, wihl, will, bihL, p_gx, NN, H3, HH);
            mma_gemm_kernel<<<grid_g, 256>>>(p_h, whhl, whll, bhhL, p_gh, NN, H3, HH);
            // GRU gates, in-place update of h
            gru_kernel<<<gru_blocks, 256>>>((const float4*)p_gx, (const float4*)p_gh,
                                            (float4*)p_h, (int)n4);
        }
    }

    // pooled mean + FC
    zero_kernel<<<1, 64>>>(p_pooled, HH / 4);
    pool_kernel<<<256, HH>>>(p_h, p_pooled, NN);
    fc_kernel<<<CC, 32>>>(p_pooled, fc_w, fc_b, out, 1.0f / (float)NN);
}

// round 7
// speedup vs baseline: 1.0950x; 1.0950x over previous
#include <cuda_runtime.h>
#include <cuda_bf16.h>
#include <math.h>
#include <stdint.h>

// Problem constants (fixed by the reference)
#define NN 50000
#define HH 256
#define TT 4
#define LL 2
#define SS 3
#define CC 3
#define H3 (3 * HH)
#define THX (TT * HH)   // 1024

// ---------------- fp32 scratch: ONE device global, carved by offsets --------
#define OFF_H0   ((size_t)0)                        // [NN*HH]  node state buf 0
#define OFF_H1   (OFF_H0  + (size_t)NN * HH)        // [NN*HH]  node state buf 1
#define OFF_WH   (OFF_H1  + (size_t)NN * HH)        // [NN*THX] per-etype transforms
#define OFF_A    (OFF_WH  + (size_t)NN * THX)       // [NN*HH]  aggregated messages
#define OFF_POOL (OFF_A   + (size_t)NN * HH)        // [HH]
#define SCRATCH_FLOATS (OFF_POOL + HH)
__device__ float s_scratch[SCRATCH_FLOATS];

// bf16 split weights (original [n][k] layout)
__device__ __nv_bfloat16 s_Whi[(size_t)LL * THX * HH];
__device__ __nv_bfloat16 s_Wlo[(size_t)LL * THX * HH];
__device__ __nv_bfloat16 s_wihi[(size_t)LL * H3 * HH];
__device__ __nv_bfloat16 s_wilo[(size_t)LL * H3 * HH];
__device__ __nv_bfloat16 s_whhi[(size_t)LL * H3 * HH];
__device__ __nv_bfloat16 s_whlo[(size_t)LL * H3 * HH];

// ---------------- generic helpers ----------------
__global__ void copy_kernel(const float* __restrict__ in, float* __restrict__ out, size_t n4) {
    size_t i = (size_t)blockIdx.x * blockDim.x + threadIdx.x;
    if (i < n4) ((float4*)out)[i] = ((const float4*)in)[i];
}

__global__ void zero_kernel(float* __restrict__ p, size_t n4) {
    size_t i = (size_t)blockIdx.x * blockDim.x + threadIdx.x;
    if (i < n4) ((float4*)p)[i] = make_float4(0.f, 0.f, 0.f, 0.f);
}

// fp32 -> bf16 hi + bf16 residual lo (same layout)
__global__ void split_kernel(const float* __restrict__ w, __nv_bfloat16* __restrict__ hi,
                             __nv_bfloat16* __restrict__ lo, int n) {
    int i = blockIdx.x * blockDim.x + threadIdx.x;
    if (i >= n) return;
    float v = w[i];
    __nv_bfloat16 h = __float2bfloat16_rn(v);
    hi[i] = h;
    lo[i] = __float2bfloat16_rn(v - __bfloat162float(h));
}

// ---------------- mma helpers ----------------
__device__ __forceinline__ void mma16816(float* c, const uint32_t* a, const uint32_t* b) {
    asm volatile(
        "mma.sync.aligned.m16n8k16.row.col.f32.bf16.bf16.f32 "
        "{%0,%1,%2,%3}, {%4,%5,%6,%7}, {%8,%9}, {%0,%1,%2,%3};"
        : "+f"(c[0]), "+f"(c[1]), "+f"(c[2]), "+f"(c[3])
        : "r"(a[0]), "r"(a[1]), "r"(a[2]), "r"(a[3]), "r"(b[0]), "r"(b[1]));
}

__device__ __forceinline__ uint32_t pack_hi2(float x, float y) {
    __nv_bfloat162 p;
    p.x = __float2bfloat16_rn(x);
    p.y = __float2bfloat16_rn(y);
    return *reinterpret_cast<uint32_t*>(&p);
}
__device__ __forceinline__ uint32_t pack_lo2(float x, float y, uint32_t hp) {
    __nv_bfloat162 h = *reinterpret_cast<__nv_bfloat162*>(&hp);
    __nv_bfloat162 p;
    p.x = __float2bfloat16_rn(x - __bfloat162float(h.x));
    p.y = __float2bfloat16_rn(y - __bfloat162float(h.y));
    return *reinterpret_cast<uint32_t*>(&p);
}

// ---------------- bf16x3 tensor-core GEMM (Wh = h @ W^T + b) ----------------
#define GBM 128
#define GBN 128
#define GBK 32
#define SROW 20

__global__ __launch_bounds__(256)
void mma_gemm_kernel(const float* __restrict__ A,
                     const __nv_bfloat16* __restrict__ Bhi,
                     const __nv_bfloat16* __restrict__ Blo,
                     const float* __restrict__ bias, float* __restrict__ C,
                     int M, int Nc, int K) {
    __shared__ uint32_t Ash[GBM][SROW];
    __shared__ uint32_t Asl[GBM][SROW];
    __shared__ uint32_t Bsh[GBN][SROW];
    __shared__ uint32_t Bsl[GBN][SROW];

    const int tid = threadIdx.x;
    const int lane = tid & 31;
    const int wid = tid >> 5;
    const int wm = (wid >> 2) * 64;
    const int wn = (wid & 3) * 32;
    const int g = lane >> 2;
    const int t = lane & 3;

    const int blockRow = blockIdx.y * GBM;
    const int blockCol = blockIdx.x * GBN;

    const uint32_t* B32h = (const uint32_t*)Bhi;
    const uint32_t* B32l = (const uint32_t*)Blo;
    const int Kw = K >> 1;

    float acc[4][4][4];
#pragma unroll
    for (int mi = 0; mi < 4; mi++)
#pragma unroll
        for (int ni = 0; ni < 4; ni++)
#pragma unroll
            for (int r = 0; r < 4; r++) acc[mi][ni][r] = 0.f;

    float4 areg[4];
    uint4 bhr[2], blr[2];

    auto load_stage = [&](int k0) {
#pragma unroll
        for (int i = 0; i < 4; i++) {
            int lin = tid + 256 * i;
            int row = lin >> 3;
            int c4 = lin & 7;
            int gm = blockRow + row;
            areg[i] = (gm < M) ? *(const float4*)&A[(size_t)gm * K + k0 + c4 * 4]
                               : make_float4(0.f, 0.f, 0.f, 0.f);
        }
#pragma unroll
        for (int i = 0; i < 2; i++) {
            int lin = tid + 256 * i;
            int row = lin >> 2;
            int ch = lin & 3;
            size_t gi = (size_t)(blockCol + row) * Kw + (k0 >> 1) + ch * 4;
            bhr[i] = *(const uint4*)&B32h[gi];
            blr[i] = *(const uint4*)&B32l[gi];
        }
    };

    auto store_stage = [&]() {
#pragma unroll
        for (int i = 0; i < 4; i++) {
            int lin = tid + 256 * i;
            int row = lin >> 3;
            int c4 = lin & 7;
            float4 v = areg[i];
            uint32_t h0 = pack_hi2(v.x, v.y);
            uint32_t h1 = pack_hi2(v.z, v.w);
            Ash[row][c4 * 2 + 0] = h0;
            Ash[row][c4 * 2 + 1] = h1;
            Asl[row][c4 * 2 + 0] = pack_lo2(v.x, v.y, h0);
            Asl[row][c4 * 2 + 1] = pack_lo2(v.z, v.w, h1);
        }
#pragma unroll
        for (int i = 0; i < 2; i++) {
            int lin = tid + 256 * i;
            int row = lin >> 2;
            int ch = lin & 3;
            *(uint4*)&Bsh[row][ch * 4] = bhr[i];
            *(uint4*)&Bsl[row][ch * 4] = blr[i];
        }
    };

    load_stage(0);
    const int nStages = K / GBK;
    for (int s = 0; s < nStages; s++) {
        store_stage();
        __syncthreads();
        if (s + 1 < nStages) load_stage((s + 1) * GBK);

#pragma unroll
        for (int ks = 0; ks < 2; ks++) {
            const int base = ks * 8;
            uint32_t ah[4][4], al[4][4], bh_[4][2], bl_[4][2];
#pragma unroll
            for (int mi = 0; mi < 4; mi++) {
                int r0 = wm + mi * 16 + g;
                ah[mi][0] = Ash[r0][base + t];
                ah[mi][1] = Ash[r0 + 8][base + t];
                ah[mi][2] = Ash[r0][base + t + 4];
                ah[mi][3] = Ash[r0 + 8][base + t + 4];
                al[mi][0] = Asl[r0][base + t];
                al[mi][1] = Asl[r0 + 8][base + t];
                al[mi][2] = Asl[r0][base + t + 4];
                al[mi][3] = Asl[r0 + 8][base + t + 4];
            }
#pragma unroll
            for (int ni = 0; ni < 4; ni++) {
                int n0 = wn + ni * 8 + g;
                bh_[ni][0] = Bsh[n0][base + t];
                bh_[ni][1] = Bsh[n0][base + t + 4];
                bl_[ni][0] = Bsl[n0][base + t];
                bl_[ni][1] = Bsl[n0][base + t + 4];
            }
#pragma unroll
            for (int mi = 0; mi < 4; mi++)
#pragma unroll
                for (int ni = 0; ni < 4; ni++) {
                    mma16816(acc[mi][ni], ah[mi], bh_[ni]);
                    mma16816(acc[mi][ni], ah[mi], bl_[ni]);
                    mma16816(acc[mi][ni], al[mi], bh_[ni]);
                }
        }
        __syncthreads();
    }

#pragma unroll
    for (int mi = 0; mi < 4; mi++) {
        int r0 = blockRow + wm + mi * 16 + g;
        int r1 = r0 + 8;
#pragma unroll
        for (int ni = 0; ni < 4; ni++) {
            int col = blockCol + wn + ni * 8 + t * 2;
            float b0 = bias ? bias[col] : 0.f;
            float b1 = bias ? bias[col + 1] : 0.f;
            if (r0 < M) {
                float2 v = make_float2(acc[mi][ni][0] + b0, acc[mi][ni][1] + b1);
                *(float2*)&C[(size_t)r0 * Nc + col] = v;
            }
            if (r1 < M) {
                float2 v = make_float2(acc[mi][ni][2] + b0, acc[mi][ni][3] + b1);
                *(float2*)&C[(size_t)r1 * Nc + col] = v;
            }
        }
    }
}

// ---------------- edge scatter (R4 proven): a[dst] += Wh[src, etype] --------
__global__ void scatter_kernel(const float* __restrict__ Wh,
                               const int* __restrict__ src,
                               const int* __restrict__ dst,
                               const int* __restrict__ et,
                               float* __restrict__ a, int E) {
    int gwarp = (int)(((size_t)blockIdx.x * blockDim.x + threadIdx.x) >> 5);
    int lane = threadIdx.x & 31;
    if (gwarp >= E) return;
    int s = __ldg(&src[gwarp]);
    int d = __ldg(&dst[gwarp]);
    int t = __ldg(&et[gwarp]);
    const float4* sp = (const float4*)(Wh + (size_t)s * THX + (size_t)t * HH);
    float4* dp = (float4*)(a + (size_t)d * HH);
#pragma unroll
    for (int i = 0; i < 2; i++) {
        float4 v = sp[lane + 32 * i];
        asm volatile("red.global.add.v4.f32 [%0], {%1,%2,%3,%4};"
                     :: "l"(dp + lane + 32 * i), "f"(v.x), "f"(v.y), "f"(v.z), "f"(v.w)
                     : "memory");
    }
}

// ---------------- fused gates: gx=a@wih^T, gh=h@whh^T, GRU -> h_new ---------
// CTA: 64 rows x 32 j-cols. TWO PASSES over K (pass 0: a×w_ih, pass 1: h×w_hh)
// reusing the same smem buffers -> 25.6 KB static smem (fits 48 KB limit).
// gx/gh never hit DRAM.
#define FM 64
#define FN 32
#define FKC 32

__global__ __launch_bounds__(256, 2)
void fused_gate_kernel(const float* __restrict__ Aa,    // a [N,256]
                       const float* __restrict__ Hh,    // h_old [N,256]
                       const __nv_bfloat16* __restrict__ wih_hi,
                       const __nv_bfloat16* __restrict__ wih_lo,
                       const __nv_bfloat16* __restrict__ whh_hi,
                       const __nv_bfloat16* __restrict__ whh_lo,
                       const float* __restrict__ b_ih,  // [768]
                       const float* __restrict__ b_hh,  // [768]
                       float* __restrict__ Hnew, int M) {
    __shared__ uint32_t Ath[FM][SROW], Atl[FM][SROW];          // A tile hi/lo (reused)
    __shared__ uint32_t Bh[3][FN][SROW], Bl[3][FN][SROW];      // 3 gate tiles (reused)

    const int tid = threadIdx.x;
    const int lane = tid & 31;
    const int wid = tid >> 5;
    const int wm = (wid >> 1) * 16;        // 4 M-groups of 16
    const int wn = (wid & 1) * 16;         // 2 N-groups of 16 (2x n8)
    const int g = lane >> 2;
    const int t = lane & 3;

    const int blockRow = blockIdx.y * FM;
    const int j0 = blockIdx.x * FN;

    // acc[o][ni][4]: o = 0..2 gx r/z/n, 3..5 gh r/z/n
    float acc[6][2][4];
#pragma unroll
    for (int o = 0; o < 6; o++)
#pragma unroll
        for (int ni = 0; ni < 2; ni++)
#pragma unroll
            for (int r = 0; r < 4; r++) acc[o][ni][r] = 0.f;

#pragma unroll
    for (int pass = 0; pass < 2; pass++) {
        const float* Ain = pass ? Hh : Aa;
        const uint32_t* Wh32 = (const uint32_t*)(pass ? whh_hi : wih_hi);
        const uint32_t* Wl32 = (const uint32_t*)(pass ? whh_lo : wih_lo);

        for (int k0 = 0; k0 < HH; k0 += FKC) {
            // load A tile: 64 rows x 8 float4 = 512, 2/thread
#pragma unroll
            for (int i = 0; i < 2; i++) {
                int lin = tid + 256 * i;
                int row = lin >> 3;
                int c4 = lin & 7;
                int gm = blockRow + row;
                float4 av = (gm < M) ? *(const float4*)&Ain[(size_t)gm * HH + k0 + c4 * 4]
                                     : make_float4(0.f, 0.f, 0.f, 0.f);
                uint32_t a0 = pack_hi2(av.x, av.y), a1 = pack_hi2(av.z, av.w);
                Ath[row][c4 * 2 + 0] = a0;
                Ath[row][c4 * 2 + 1] = a1;
                Atl[row][c4 * 2 + 0] = pack_lo2(av.x, av.y, a0);
                Atl[row][c4 * 2 + 1] = pack_lo2(av.z, av.w, a1);
            }
            // load B tiles: 3 mats x 32 rows x 4 uint4 = 384 uint4; tid + tid<128
#pragma unroll
            for (int i = 0; i < 2; i++) {
                int lin = tid + 256 * i;
                if (lin < 384) {
                    int mat = lin >> 7;
                    int rem = lin & 127;
                    int row = rem >> 2;
                    int ch = rem & 3;
                    size_t idx = (size_t)(mat * HH + j0 + row) * (HH / 2) + (k0 >> 1) + ch * 4;
                    *(uint4*)&Bh[mat][row][ch * 4] = *(const uint4*)&Wh32[idx];
                    *(uint4*)&Bl[mat][row][ch * 4] = *(const uint4*)&Wl32[idx];
                }
            }
            __syncthreads();

#pragma unroll
            for (int ks = 0; ks < 2; ks++) {
                const int base = ks * 8;
                uint32_t ah[4], al[4];
                int r0 = wm + g;
                ah[0] = Ath[r0][base + t];
                ah[1] = Ath[r0 + 8][base + t];
                ah[2] = Ath[r0][base + t + 4];
                ah[3] = Ath[r0 + 8][base + t + 4];
                al[0] = Atl[r0][base + t];
                al[1] = Atl[r0 + 8][base + t];
                al[2] = Atl[r0][base + t + 4];
                al[3] = Atl[r0 + 8][base + t + 4];

#pragma unroll
                for (int o = 0; o < 3; o++) {
                    float* ac0 = acc[pass * 3 + o][0];
                    float* ac1 = acc[pass * 3 + o][1];
#pragma unroll
                    for (int ni = 0; ni < 2; ni++) {
                        int n0 = wn + ni * 8 + g;
                        uint32_t bh_[2], bl_[2];
                        bh_[0] = Bh[o][n0][base + t];
                        bh_[1] = Bh[o][n0][base + t + 4];
                        bl_[0] = Bl[o][n0][base + t];
                        bl_[1] = Bl[o][n0][base + t + 4];
                        float* ac = ni ? ac1 : ac0;
                        mma16816(ac, ah, bh_);
                        mma16816(ac, ah, bl_);
                        mma16816(ac, al, bh_);
                    }
                }
            }
            __syncthreads();
        }
    }

    // epilogue: GRU gates
#pragma unroll
    for (int ni = 0; ni < 2; ni++) {
        int jc = j0 + wn + ni * 8 + t * 2;
        float2 bir = *(const float2*)&b_ih[jc];
        float2 biz = *(const float2*)&b_ih[HH + jc];
        float2 bin = *(const float2*)&b_ih[2 * HH + jc];
        float2 bhr = *(const float2*)&b_hh[jc];
        float2 bhz = *(const float2*)&b_hh[HH + jc];
        float2 bhn = *(const float2*)&b_hh[2 * HH + jc];
#pragma unroll
        for (int half = 0; half < 2; half++) {
            int row = blockRow + wm + g + half * 8;
            if (row >= M) continue;
            float2 hold = *(const float2*)&Hh[(size_t)row * HH + jc];
            int e = half * 2;
            float r0 = 1.f / (1.f + expf(-(acc[0][ni][e] + bir.x + acc[3][ni][e] + bhr.x)));
            float z0 = 1.f / (1.f + expf(-(acc[1][ni][e] + biz.x + acc[4][ni][e] + bhz.x)));
            float n0 = tanhf(acc[2][ni][e] + bin.x + r0 * (acc[5][ni][e] + bhn.x));
            float r1 = 1.f / (1.f + expf(-(acc[0][ni][e + 1] + bir.y + acc[3][ni][e + 1] + bhr.y)));
            float z1 = 1.f / (1.f + expf(-(acc[1][ni][e + 1] + biz.y + acc[4][ni][e + 1] + bhz.y)));
            float n1 = tanhf(acc[2][ni][e + 1] + bin.y + r1 * (acc[5][ni][e + 1] + bhn.y));
            float2 hv;
            hv.x = (1.f - z0) * n0 + z0 * hold.x;
            hv.y = (1.f - z1) * n1 + z1 * hold.y;
            *(float2*)&Hnew[(size_t)row * HH + jc] = hv;
        }
    }
}

// ---------------- pooling + FC ----------------
__global__ void pool_kernel(const float* __restrict__ h, float* __restrict__ pooled, int n) {
    int k = threadIdx.x;
    float acc = 0.f;
    for (int r = blockIdx.x; r < n; r += gridDim.x)
        acc += h[(size_t)r * HH + k];
    atomicAdd(&pooled[k], acc);
}

__global__ void fc_kernel(const float* __restrict__ pooled, const float* __restrict__ fc_w,
                          const float* __restrict__ fc_b, float* __restrict__ out, float invN) {
    int c = blockIdx.x;
    int lane = threadIdx.x;
    float acc = 0.f;
    for (int k = lane; k < HH; k += 32) acc += pooled[k] * fc_w[c * HH + k];
#pragma unroll
    for (int o = 16; o; o >>= 1) acc += __shfl_xor_sync(0xffffffffu, acc, o);
    if (lane == 0) out[c] = acc * invN + fc_b[c];
}

// ---------------- host orchestration ----------------
extern "C" void kernel_launch(void* const* d_in, const int* in_sizes, int n_in,
                              void* d_out, int out_size) {
    const float* x      = (const float*)d_in[0];
    const int*   src    = (const int*)d_in[1];
    const int*   dst    = (const int*)d_in[2];
    const int*   etype  = (const int*)d_in[3];
    const float* W_lin  = (const float*)d_in[4];
    const float* b_lin  = (const float*)d_in[5];
    const float* w_ih   = (const float*)d_in[6];
    const float* w_hh   = (const float*)d_in[7];
    const float* b_ih   = (const float*)d_in[8];
    const float* b_hh   = (const float*)d_in[9];
    const float* fc_w   = (const float*)d_in[10];
    const float* fc_b   = (const float*)d_in[11];
    float* out = (float*)d_out;

    const int E = in_sizes[1];

    float* base = nullptr;
    cudaGetSymbolAddress((void**)&base, s_scratch);
    float* p_hbuf[2] = {base + OFF_H0, base + OFF_H1};
    float* p_Wh     = base + OFF_WH;
    float* p_a      = base + OFF_A;
    float* p_pooled = base + OFF_POOL;

    __nv_bfloat16 *p_Whi, *p_Wlo, *p_wihi, *p_wilo, *p_whhi, *p_whlo;
    cudaGetSymbolAddress((void**)&p_Whi, s_Whi);
    cudaGetSymbolAddress((void**)&p_Wlo, s_Wlo);
    cudaGetSymbolAddress((void**)&p_wihi, s_wihi);
    cudaGetSymbolAddress((void**)&p_wilo, s_wilo);
    cudaGetSymbolAddress((void**)&p_whhi, s_whhi);
    cudaGetSymbolAddress((void**)&p_whlo, s_whlo);

    // ---- weight splits (original [n][k] layout) ----
    {
        int nW = LL * THX * HH;
        int nG = LL * H3 * HH;
        split_kernel<<<(nW + 255) / 256, 256>>>(W_lin, p_Whi, p_Wlo, nW);
        split_kernel<<<(nG + 255) / 256, 256>>>(w_ih, p_wihi, p_wilo, nG);
        split_kernel<<<(nG + 255) / 256, 256>>>(w_hh, p_whhi, p_whlo, nG);
    }

    // ---- h0 = x ----
    size_t n4 = (size_t)NN * HH / 4;
    copy_kernel<<<(int)((n4 + 255) / 256), 256>>>(x, p_hbuf[0], n4);

    dim3 grid_wh(THX / GBN, (NN + GBM - 1) / GBM);     // (8, 391)
    dim3 grid_f(HH / FN, (NN + FM - 1) / FM);          // (8, 782)
    int scatter_blocks = (int)(((size_t)E * 32 + 255) / 256);

    int cur = 0;
    for (int l = 0; l < LL; l++) {
        const float* blinL = b_lin + (size_t)l * THX;
        const float* bihL  = b_ih + (size_t)l * H3;
        const float* bhhL  = b_hh + (size_t)l * H3;
        const __nv_bfloat16* Whl  = p_Whi + (size_t)l * THX * HH;
        const __nv_bfloat16* Wll  = p_Wlo + (size_t)l * THX * HH;
        const __nv_bfloat16* wihl = p_wihi + (size_t)l * H3 * HH;
        const __nv_bfloat16* will = p_wilo + (size_t)l * H3 * HH;
        const __nv_bfloat16* whhl = p_whhi + (size_t)l * H3 * HH;
        const __nv_bfloat16* whll = p_whlo + (size_t)l * H3 * HH;

        for (int s = 0; s < SS; s++) {
            float* hcur = p_hbuf[cur];
            float* hnext = p_hbuf[cur ^ 1];
            // Wh = h @ W^T + b_lin   [N, T*H]
            mma_gemm_kernel<<<grid_wh, 256>>>(hcur, Whl, Wll, blinL, p_Wh, NN, THX, HH);
            // a = 0 ; a[dst] += Wh[src, etype]
            zero_kernel<<<(int)((n4 + 255) / 256), 256>>>(p_a, n4);
            scatter_kernel<<<scatter_blocks, 256>>>(p_Wh, src, dst, etype, p_a, E);
            // fused gates: h_new = GRU(a, h)
            fused_gate_kernel<<<grid_f, 256>>>(p_a, hcur, wihl, will, whhl, whll,
                                               bihL, bhhL, hnext, NN);
            cur ^= 1;
        }
    }

    // pooled mean + FC
    zero_kernel<<<1, 64>>>(p_pooled, HH / 4);
    pool_kernel<<<256, HH>>>(p_hbuf[cur], p_pooled, NN);
    fc_kernel<<<CC, 32>>>(p_pooled, fc_w, fc_b, out, 1.0f / (float)NN);
}